// round 5
// baseline (speedup 1.0000x reference)
#include <cuda_runtime.h>
#include <cstdint>

// ---------------------------------------------------------------------------
// ModernNCA forward, fp32, FFMA2 (fma.rn.f32x2) SIMT GEMMs.
// Pipeline:
//   1. hidden = relu(sub_x @ W1 + b1)            [30000,512]
//   2. sh     = relu(hidden @ W2 + b2), s2=||sh||^2   [30000,128]
//   3. hidden = relu(x @ W1 + b1)                [1024,512]
//   4. h      = relu(hidden @ W2 + b2), x2=||h||^2    [1024,128]
//   5. dist[b,n] = sqrt(max(x2+s2-2 h.sh,0)+eps) [1024,30000]
//   6. out[b] = sum(exp(min-dist)*y)/sum(exp(min-dist))
// ---------------------------------------------------------------------------

#define BM 128
#define BN 128
#define BK 16
#define TM 8
#define TN 8
#define TPB 256

static __device__ float g_hidden[30000 * 512];          // 61.4 MB scratch
static __device__ float g_sh[30000 * 128];              // 15.4 MB
static __device__ float g_h[1024 * 128];
static __device__ float g_s2[30000];
static __device__ float g_x2[1024];
static __device__ float g_dist[30720000];               // 1024*30000, 122.9 MB

// ---- packed f32x2 helpers --------------------------------------------------
__device__ __forceinline__ void fma2(unsigned long long& acc,
                                     unsigned long long a,
                                     unsigned long long b) {
    asm("fma.rn.f32x2 %0, %1, %2, %0;" : "+l"(acc) : "l"(a), "l"(b));
}
__device__ __forceinline__ unsigned long long pack2(float lo, float hi) {
    unsigned long long r;
    asm("mov.b64 %0, {%1, %2};" : "=l"(r) : "f"(lo), "f"(hi));
    return r;
}
__device__ __forceinline__ float2 unpack2(unsigned long long v) {
    float2 f;
    asm("mov.b64 {%0, %1}, %2;" : "=f"(f.x), "=f"(f.y) : "l"(v));
    return f;
}

// ---------------------------------------------------------------------------
// GEMM: C[M,N] = relu(A[M,K] @ B[K,N] + bias[N]); optional row sum-of-squares.
// A row-major lda=K, B row-major ldb=N, C row-major ldc=N.
// ---------------------------------------------------------------------------
template <bool SUMSQ>
__global__ void __launch_bounds__(TPB, 2)
gemm_bias_relu(const float* __restrict__ A, const float* __restrict__ B,
               const float* __restrict__ bias, float* __restrict__ C,
               float* __restrict__ sumsq,
               int M, int N, int K, int lda, int ldb, int ldc) {
    __shared__ float As[BK][BM];
    __shared__ float Bs[BK][BN];

    const int blockN = blockIdx.x * BN;
    const int blockM = blockIdx.y * BM;
    const int tx = threadIdx.x & 15;
    const int ty = threadIdx.x >> 4;

    unsigned long long acc[TM][TN / 2];
#pragma unroll
    for (int i = 0; i < TM; i++)
#pragma unroll
        for (int j = 0; j < TN / 2; j++) acc[i][j] = 0ull;

    for (int k0 = 0; k0 < K; k0 += BK) {
        // load A tile (transposed into As[k][m])
#pragma unroll
        for (int l = threadIdx.x; l < BM * BK / 4; l += TPB) {
            int row = l >> 2;           // BK/4 == 4 float4 per row
            int kq  = l & 3;
            float4 v = make_float4(0.f, 0.f, 0.f, 0.f);
            int grow = blockM + row;
            if (grow < M)
                v = *(const float4*)&A[(size_t)grow * lda + k0 + kq * 4];
            As[kq * 4 + 0][row] = v.x;
            As[kq * 4 + 1][row] = v.y;
            As[kq * 4 + 2][row] = v.z;
            As[kq * 4 + 3][row] = v.w;
        }
        // load B tile (natural layout Bs[k][n])
#pragma unroll
        for (int l = threadIdx.x; l < BK * BN / 4; l += TPB) {
            int kk = l >> 5;            // BN/4 == 32
            int nq = l & 31;
            float4 v = *(const float4*)&B[(size_t)(k0 + kk) * ldb + blockN + nq * 4];
            *(float4*)&Bs[kk][nq * 4] = v;
        }
        __syncthreads();

#pragma unroll
        for (int k = 0; k < BK; k++) {
            float4 a0 = *(float4*)&As[k][ty * TM];
            float4 a1 = *(float4*)&As[k][ty * TM + 4];
            float4 b0 = *(float4*)&Bs[k][tx * TN];
            float4 b1 = *(float4*)&Bs[k][tx * TN + 4];
            unsigned long long bp[4] = {pack2(b0.x, b0.y), pack2(b0.z, b0.w),
                                        pack2(b1.x, b1.y), pack2(b1.z, b1.w)};
            float av[8] = {a0.x, a0.y, a0.z, a0.w, a1.x, a1.y, a1.z, a1.w};
#pragma unroll
            for (int i = 0; i < TM; i++) {
                unsigned long long ad = pack2(av[i], av[i]);
#pragma unroll
                for (int jp = 0; jp < TN / 2; jp++) fma2(acc[i][jp], ad, bp[jp]);
            }
        }
        __syncthreads();
    }

    // epilogue: bias + relu (+ optional row sumsq)
#pragma unroll
    for (int i = 0; i < TM; i++) {
        int grow = blockM + ty * TM + i;
        float ss = 0.f;
#pragma unroll
        for (int jp = 0; jp < TN / 2; jp++) {
            int col = blockN + tx * TN + 2 * jp;
            float2 c = unpack2(acc[i][jp]);
            c.x = fmaxf(c.x + bias[col], 0.f);
            c.y = fmaxf(c.y + bias[col + 1], 0.f);
            if (grow < M)
                *(float2*)&C[(size_t)grow * ldc + col] = c;
            if (SUMSQ) ss += c.x * c.x + c.y * c.y;
        }
        if (SUMSQ) {
            // reduce across the 16 tx lanes (lane = tid%32, tx = lane%16)
#pragma unroll
            for (int off = 8; off > 0; off >>= 1)
                ss += __shfl_down_sync(0xffffffffu, ss, off, 16);
            if (tx == 0 && grow < M) sumsq[grow] = ss;
        }
    }
}

// ---------------------------------------------------------------------------
// Distance GEMM: D[b,n] = sqrt(max(x2[b]+s2[n]-2*(h[b].sh[n]),0)+eps)
// A = h [M,K] row-major, Bm = sh [N,K] row-major (both K-major -> A @ B^T)
// ---------------------------------------------------------------------------
__global__ void __launch_bounds__(TPB, 2)
dist_kernel(const float* __restrict__ A, const float* __restrict__ Bm,
            const float* __restrict__ x2, const float* __restrict__ s2,
            float* __restrict__ D, int M, int N, int K) {
    __shared__ float As[BK][BM];
    __shared__ float Bs[BK][BN];

    const int blockN = blockIdx.x * BN;
    const int blockM = blockIdx.y * BM;
    const int tx = threadIdx.x & 15;
    const int ty = threadIdx.x >> 4;

    unsigned long long acc[TM][TN / 2];
#pragma unroll
    for (int i = 0; i < TM; i++)
#pragma unroll
        for (int j = 0; j < TN / 2; j++) acc[i][j] = 0ull;

    for (int k0 = 0; k0 < K; k0 += BK) {
#pragma unroll
        for (int l = threadIdx.x; l < BM * BK / 4; l += TPB) {
            int row = l >> 2;
            int kq  = l & 3;
            float4 v = make_float4(0.f, 0.f, 0.f, 0.f);
            int grow = blockM + row;
            if (grow < M)
                v = *(const float4*)&A[(size_t)grow * K + k0 + kq * 4];
            As[kq * 4 + 0][row] = v.x;
            As[kq * 4 + 1][row] = v.y;
            As[kq * 4 + 2][row] = v.z;
            As[kq * 4 + 3][row] = v.w;
        }
#pragma unroll
        for (int l = threadIdx.x; l < BN * BK / 4; l += TPB) {
            int row = l >> 2;
            int kq  = l & 3;
            float4 v = make_float4(0.f, 0.f, 0.f, 0.f);
            int grown = blockN + row;
            if (grown < N)
                v = *(const float4*)&Bm[(size_t)grown * K + k0 + kq * 4];
            Bs[kq * 4 + 0][row] = v.x;
            Bs[kq * 4 + 1][row] = v.y;
            Bs[kq * 4 + 2][row] = v.z;
            Bs[kq * 4 + 3][row] = v.w;
        }
        __syncthreads();

#pragma unroll
        for (int k = 0; k < BK; k++) {
            float4 a0 = *(float4*)&As[k][ty * TM];
            float4 a1 = *(float4*)&As[k][ty * TM + 4];
            float4 b0 = *(float4*)&Bs[k][tx * TN];
            float4 b1 = *(float4*)&Bs[k][tx * TN + 4];
            unsigned long long bp[4] = {pack2(b0.x, b0.y), pack2(b0.z, b0.w),
                                        pack2(b1.x, b1.y), pack2(b1.z, b1.w)};
            float av[8] = {a0.x, a0.y, a0.z, a0.w, a1.x, a1.y, a1.z, a1.w};
#pragma unroll
            for (int i = 0; i < TM; i++) {
                unsigned long long ad = pack2(av[i], av[i]);
#pragma unroll
                for (int jp = 0; jp < TN / 2; jp++) fma2(acc[i][jp], ad, bp[jp]);
            }
        }
        __syncthreads();
    }

#pragma unroll
    for (int i = 0; i < TM; i++) {
        int grow = blockM + ty * TM + i;
        if (grow >= M) continue;
        float x2v = x2[grow];
#pragma unroll
        for (int jp = 0; jp < TN / 2; jp++) {
            int gcol = blockN + tx * TN + 2 * jp;
            if (gcol >= N) continue;
            float2 c = unpack2(acc[i][jp]);
            float d2x = fmaxf(x2v + s2[gcol]     - 2.0f * c.x, 0.f);
            float d2y = fmaxf(x2v + s2[gcol + 1] - 2.0f * c.y, 0.f);
            float2 dd;
            dd.x = sqrtf(d2x + 1e-8f);
            dd.y = sqrtf(d2y + 1e-8f);
            *(float2*)&D[(size_t)grow * N + gcol] = dd;
        }
    }
}

// ---------------------------------------------------------------------------
// Row softmax(-dist) @ y : out[b] = sum(exp(min-dist)*y) / sum(exp(min-dist))
// ---------------------------------------------------------------------------
__global__ void softmax_out_kernel(const float* __restrict__ dist,
                                   const float* __restrict__ y,
                                   float* __restrict__ out, int N) {
    const int b = blockIdx.x;
    const float4* row = (const float4*)(dist + (size_t)b * N);
    const float4* y4  = (const float4*)y;
    const int N4 = N / 4;

    float m = 3.4e38f;
    for (int i = threadIdx.x; i < N4; i += TPB) {
        float4 v = row[i];
        m = fminf(m, fminf(fminf(v.x, v.y), fminf(v.z, v.w)));
    }
    __shared__ float red[TPB];
    red[threadIdx.x] = m;
    __syncthreads();
    for (int s = TPB / 2; s > 0; s >>= 1) {
        if (threadIdx.x < s)
            red[threadIdx.x] = fminf(red[threadIdx.x], red[threadIdx.x + s]);
        __syncthreads();
    }
    const float minv = red[0];
    __syncthreads();

    float ssum = 0.f, wsum = 0.f;
    for (int i = threadIdx.x; i < N4; i += TPB) {
        float4 v  = row[i];
        float4 yv = y4[i];
        float e0 = __expf(minv - v.x);
        float e1 = __expf(minv - v.y);
        float e2 = __expf(minv - v.z);
        float e3 = __expf(minv - v.w);
        ssum += (e0 + e1) + (e2 + e3);
        wsum += (e0 * yv.x + e1 * yv.y) + (e2 * yv.z + e3 * yv.w);
    }
    __shared__ float rs[TPB];
    __shared__ float rw[TPB];
    rs[threadIdx.x] = ssum;
    rw[threadIdx.x] = wsum;
    __syncthreads();
    for (int s = TPB / 2; s > 0; s >>= 1) {
        if (threadIdx.x < s) {
            rs[threadIdx.x] += rs[threadIdx.x + s];
            rw[threadIdx.x] += rw[threadIdx.x + s];
        }
        __syncthreads();
    }
    if (threadIdx.x == 0) out[b] = rw[0] / rs[0];
}

// ---------------------------------------------------------------------------
extern "C" void kernel_launch(void* const* d_in, const int* in_sizes, int n_in,
                              void* d_out, int out_size) {
    const float* x     = (const float*)d_in[0];  // [1024,256]
    const float* sub_x = (const float*)d_in[1];  // [30000,256]
    const float* sub_y = (const float*)d_in[2];  // [30000]
    const float* W1    = (const float*)d_in[3];  // [256,512]
    const float* b1    = (const float*)d_in[4];  // [512]
    const float* W2    = (const float*)d_in[5];  // [512,128]
    const float* b2    = (const float*)d_in[6];  // [128]
    float* out = (float*)d_out;                  // [1024]

    const int B = 1024, N = 30000, D = 256, H1 = 512, H2 = 128;

    float *hidden, *sh, *h, *s2, *x2, *dist;
    cudaGetSymbolAddress((void**)&hidden, g_hidden);
    cudaGetSymbolAddress((void**)&sh, g_sh);
    cudaGetSymbolAddress((void**)&h, g_h);
    cudaGetSymbolAddress((void**)&s2, g_s2);
    cudaGetSymbolAddress((void**)&x2, g_x2);
    cudaGetSymbolAddress((void**)&dist, g_dist);

    dim3 t(TPB);
    const int nTilesN = (N + BM - 1) / BM;  // 235 row tiles for the sub set

    // sub_x path
    gemm_bias_relu<false><<<dim3(H1 / BN, nTilesN), t>>>(
        sub_x, W1, b1, hidden, nullptr, N, H1, D, D, H1, H1);
    gemm_bias_relu<true><<<dim3(H2 / BN, nTilesN), t>>>(
        hidden, W2, b2, sh, s2, N, H2, H1, H1, H2, H2);

    // x path (reuses hidden scratch; stream-ordered after step 2)
    gemm_bias_relu<false><<<dim3(H1 / BN, B / BM), t>>>(
        x, W1, b1, hidden, nullptr, B, H1, D, D, H1, H1);
    gemm_bias_relu<true><<<dim3(H2 / BN, B / BM), t>>>(
        hidden, W2, b2, h, x2, B, H2, H1, H1, H2, H2);

    // pairwise distances
    dist_kernel<<<dim3((N + BN - 1) / BN, B / BM), t>>>(
        h, sh, x2, s2, dist, B, N, H2);

    // softmax(-dist) @ sub_y
    softmax_out_kernel<<<B, TPB>>>(dist, sub_y, out, N);

    (void)in_sizes; (void)n_in; (void)out_size;
}

// round 7
// speedup vs baseline: 1.0032x; 1.0032x over previous
#include <cuda_runtime.h>
#include <cstdint>

// ---------------------------------------------------------------------------
// ModernNCA forward, fp32, FFMA2 (fma.rn.f32x2) SIMT GEMMs.
// Pipeline:
//   1. hidden = relu(sub_x @ W1 + b1)            [30000,512]
//   2. sh     = relu(hidden @ W2 + b2), s2=||sh||^2   [30000,128]
//   3. hidden = relu(x @ W1 + b1)                [1024,512]
//   4. h      = relu(hidden @ W2 + b2), x2=||h||^2    [1024,128]
//   5. dist[b,n] = sqrt(max(x2+s2-2 h.sh,0)+eps) [1024,30000]
//   6. out[b] = sum(exp(min-dist)*y)/sum(exp(min-dist))
// ---------------------------------------------------------------------------

#define BM 128
#define BN 128
#define BK 16
#define TM 8
#define TN 8
#define TPB 256

static __device__ float g_hidden[30000 * 512];          // 61.4 MB scratch
static __device__ float g_sh[30000 * 128];              // 15.4 MB
static __device__ float g_h[1024 * 128];
static __device__ float g_s2[30000];
static __device__ float g_x2[1024];
static __device__ float g_dist[30720000];               // 1024*30000, 122.9 MB

// ---- packed f32x2 helpers --------------------------------------------------
__device__ __forceinline__ void fma2(unsigned long long& acc,
                                     unsigned long long a,
                                     unsigned long long b) {
    asm("fma.rn.f32x2 %0, %1, %2, %0;" : "+l"(acc) : "l"(a), "l"(b));
}
__device__ __forceinline__ unsigned long long pack2(float lo, float hi) {
    unsigned long long r;
    asm("mov.b64 %0, {%1, %2};" : "=l"(r) : "f"(lo), "f"(hi));
    return r;
}
__device__ __forceinline__ float2 unpack2(unsigned long long v) {
    float2 f;
    asm("mov.b64 {%0, %1}, %2;" : "=f"(f.x), "=f"(f.y) : "l"(v));
    return f;
}

// ---------------------------------------------------------------------------
// GEMM: C[M,N] = relu(A[M,K] @ B[K,N] + bias[N]); optional row sum-of-squares.
// A row-major lda=K, B row-major ldb=N, C row-major ldc=N.
// ---------------------------------------------------------------------------
template <bool SUMSQ>
__global__ void __launch_bounds__(TPB, 2)
gemm_bias_relu(const float* __restrict__ A, const float* __restrict__ B,
               const float* __restrict__ bias, float* __restrict__ C,
               float* __restrict__ sumsq,
               int M, int N, int K, int lda, int ldb, int ldc) {
    __shared__ float As[BK][BM];
    __shared__ float Bs[BK][BN];

    const int blockN = blockIdx.x * BN;
    const int blockM = blockIdx.y * BM;
    const int tx = threadIdx.x & 15;
    const int ty = threadIdx.x >> 4;

    unsigned long long acc[TM][TN / 2];
#pragma unroll
    for (int i = 0; i < TM; i++)
#pragma unroll
        for (int j = 0; j < TN / 2; j++) acc[i][j] = 0ull;

    for (int k0 = 0; k0 < K; k0 += BK) {
        // load A tile (transposed into As[k][m])
#pragma unroll
        for (int l = threadIdx.x; l < BM * BK / 4; l += TPB) {
            int row = l >> 2;           // BK/4 == 4 float4 per row
            int kq  = l & 3;
            float4 v = make_float4(0.f, 0.f, 0.f, 0.f);
            int grow = blockM + row;
            if (grow < M)
                v = *(const float4*)&A[(size_t)grow * lda + k0 + kq * 4];
            As[kq * 4 + 0][row] = v.x;
            As[kq * 4 + 1][row] = v.y;
            As[kq * 4 + 2][row] = v.z;
            As[kq * 4 + 3][row] = v.w;
        }
        // load B tile (natural layout Bs[k][n])
#pragma unroll
        for (int l = threadIdx.x; l < BK * BN / 4; l += TPB) {
            int kk = l >> 5;            // BN/4 == 32
            int nq = l & 31;
            float4 v = *(const float4*)&B[(size_t)(k0 + kk) * ldb + blockN + nq * 4];
            *(float4*)&Bs[kk][nq * 4] = v;
        }
        __syncthreads();

#pragma unroll
        for (int k = 0; k < BK; k++) {
            float4 a0 = *(float4*)&As[k][ty * TM];
            float4 a1 = *(float4*)&As[k][ty * TM + 4];
            float4 b0 = *(float4*)&Bs[k][tx * TN];
            float4 b1 = *(float4*)&Bs[k][tx * TN + 4];
            unsigned long long bp[4] = {pack2(b0.x, b0.y), pack2(b0.z, b0.w),
                                        pack2(b1.x, b1.y), pack2(b1.z, b1.w)};
            float av[8] = {a0.x, a0.y, a0.z, a0.w, a1.x, a1.y, a1.z, a1.w};
#pragma unroll
            for (int i = 0; i < TM; i++) {
                unsigned long long ad = pack2(av[i], av[i]);
#pragma unroll
                for (int jp = 0; jp < TN / 2; jp++) fma2(acc[i][jp], ad, bp[jp]);
            }
        }
        __syncthreads();
    }

    // epilogue: bias + relu (+ optional row sumsq)
#pragma unroll
    for (int i = 0; i < TM; i++) {
        int grow = blockM + ty * TM + i;
        float ss = 0.f;
#pragma unroll
        for (int jp = 0; jp < TN / 2; jp++) {
            int col = blockN + tx * TN + 2 * jp;
            float2 c = unpack2(acc[i][jp]);
            c.x = fmaxf(c.x + bias[col], 0.f);
            c.y = fmaxf(c.y + bias[col + 1], 0.f);
            if (grow < M)
                *(float2*)&C[(size_t)grow * ldc + col] = c;
            if (SUMSQ) ss += c.x * c.x + c.y * c.y;
        }
        if (SUMSQ) {
            // reduce across the 16 tx lanes (lane = tid%32, tx = lane%16)
#pragma unroll
            for (int off = 8; off > 0; off >>= 1)
                ss += __shfl_down_sync(0xffffffffu, ss, off, 16);
            if (tx == 0 && grow < M) sumsq[grow] = ss;
        }
    }
}

// ---------------------------------------------------------------------------
// Distance GEMM: D[b,n] = sqrt(max(x2[b]+s2[n]-2*(h[b].sh[n]),0)+eps)
// A = h [M,K] row-major, Bm = sh [N,K] row-major (both K-major -> A @ B^T)
// ---------------------------------------------------------------------------
__global__ void __launch_bounds__(TPB, 2)
dist_kernel(const float* __restrict__ A, const float* __restrict__ Bm,
            const float* __restrict__ x2, const float* __restrict__ s2,
            float* __restrict__ D, int M, int N, int K) {
    __shared__ float As[BK][BM];
    __shared__ float Bs[BK][BN];

    const int blockN = blockIdx.x * BN;
    const int blockM = blockIdx.y * BM;
    const int tx = threadIdx.x & 15;
    const int ty = threadIdx.x >> 4;

    unsigned long long acc[TM][TN / 2];
#pragma unroll
    for (int i = 0; i < TM; i++)
#pragma unroll
        for (int j = 0; j < TN / 2; j++) acc[i][j] = 0ull;

    for (int k0 = 0; k0 < K; k0 += BK) {
#pragma unroll
        for (int l = threadIdx.x; l < BM * BK / 4; l += TPB) {
            int row = l >> 2;
            int kq  = l & 3;
            float4 v = make_float4(0.f, 0.f, 0.f, 0.f);
            int grow = blockM + row;
            if (grow < M)
                v = *(const float4*)&A[(size_t)grow * K + k0 + kq * 4];
            As[kq * 4 + 0][row] = v.x;
            As[kq * 4 + 1][row] = v.y;
            As[kq * 4 + 2][row] = v.z;
            As[kq * 4 + 3][row] = v.w;
        }
#pragma unroll
        for (int l = threadIdx.x; l < BN * BK / 4; l += TPB) {
            int row = l >> 2;
            int kq  = l & 3;
            float4 v = make_float4(0.f, 0.f, 0.f, 0.f);
            int grown = blockN + row;
            if (grown < N)
                v = *(const float4*)&Bm[(size_t)grown * K + k0 + kq * 4];
            Bs[kq * 4 + 0][row] = v.x;
            Bs[kq * 4 + 1][row] = v.y;
            Bs[kq * 4 + 2][row] = v.z;
            Bs[kq * 4 + 3][row] = v.w;
        }
        __syncthreads();

#pragma unroll
        for (int k = 0; k < BK; k++) {
            float4 a0 = *(float4*)&As[k][ty * TM];
            float4 a1 = *(float4*)&As[k][ty * TM + 4];
            float4 b0 = *(float4*)&Bs[k][tx * TN];
            float4 b1 = *(float4*)&Bs[k][tx * TN + 4];
            unsigned long long bp[4] = {pack2(b0.x, b0.y), pack2(b0.z, b0.w),
                                        pack2(b1.x, b1.y), pack2(b1.z, b1.w)};
            float av[8] = {a0.x, a0.y, a0.z, a0.w, a1.x, a1.y, a1.z, a1.w};
#pragma unroll
            for (int i = 0; i < TM; i++) {
                unsigned long long ad = pack2(av[i], av[i]);
#pragma unroll
                for (int jp = 0; jp < TN / 2; jp++) fma2(acc[i][jp], ad, bp[jp]);
            }
        }
        __syncthreads();
    }

#pragma unroll
    for (int i = 0; i < TM; i++) {
        int grow = blockM + ty * TM + i;
        if (grow >= M) continue;
        float x2v = x2[grow];
#pragma unroll
        for (int jp = 0; jp < TN / 2; jp++) {
            int gcol = blockN + tx * TN + 2 * jp;
            if (gcol >= N) continue;
            float2 c = unpack2(acc[i][jp]);
            float d2x = fmaxf(x2v + s2[gcol]     - 2.0f * c.x, 0.f);
            float d2y = fmaxf(x2v + s2[gcol + 1] - 2.0f * c.y, 0.f);
            float2 dd;
            dd.x = sqrtf(d2x + 1e-8f);
            dd.y = sqrtf(d2y + 1e-8f);
            *(float2*)&D[(size_t)grow * N + gcol] = dd;
        }
    }
}

// ---------------------------------------------------------------------------
// Row softmax(-dist) @ y : out[b] = sum(exp(min-dist)*y) / sum(exp(min-dist))
// ---------------------------------------------------------------------------
__global__ void softmax_out_kernel(const float* __restrict__ dist,
                                   const float* __restrict__ y,
                                   float* __restrict__ out, int N) {
    const int b = blockIdx.x;
    const float4* row = (const float4*)(dist + (size_t)b * N);
    const float4* y4  = (const float4*)y;
    const int N4 = N / 4;

    float m = 3.4e38f;
    for (int i = threadIdx.x; i < N4; i += TPB) {
        float4 v = row[i];
        m = fminf(m, fminf(fminf(v.x, v.y), fminf(v.z, v.w)));
    }
    __shared__ float red[TPB];
    red[threadIdx.x] = m;
    __syncthreads();
    for (int s = TPB / 2; s > 0; s >>= 1) {
        if (threadIdx.x < s)
            red[threadIdx.x] = fminf(red[threadIdx.x], red[threadIdx.x + s]);
        __syncthreads();
    }
    const float minv = red[0];
    __syncthreads();

    float ssum = 0.f, wsum = 0.f;
    for (int i = threadIdx.x; i < N4; i += TPB) {
        float4 v  = row[i];
        float4 yv = y4[i];
        float e0 = __expf(minv - v.x);
        float e1 = __expf(minv - v.y);
        float e2 = __expf(minv - v.z);
        float e3 = __expf(minv - v.w);
        ssum += (e0 + e1) + (e2 + e3);
        wsum += (e0 * yv.x + e1 * yv.y) + (e2 * yv.z + e3 * yv.w);
    }
    __shared__ float rs[TPB];
    __shared__ float rw[TPB];
    rs[threadIdx.x] = ssum;
    rw[threadIdx.x] = wsum;
    __syncthreads();
    for (int s = TPB / 2; s > 0; s >>= 1) {
        if (threadIdx.x < s) {
            rs[threadIdx.x] += rs[threadIdx.x + s];
            rw[threadIdx.x] += rw[threadIdx.x + s];
        }
        __syncthreads();
    }
    if (threadIdx.x == 0) out[b] = rw[0] / rs[0];
}

// ---------------------------------------------------------------------------
extern "C" void kernel_launch(void* const* d_in, const int* in_sizes, int n_in,
                              void* d_out, int out_size) {
    const float* x     = (const float*)d_in[0];  // [1024,256]
    const float* sub_x = (const float*)d_in[1];  // [30000,256]
    const float* sub_y = (const float*)d_in[2];  // [30000]
    const float* W1    = (const float*)d_in[3];  // [256,512]
    const float* b1    = (const float*)d_in[4];  // [512]
    const float* W2    = (const float*)d_in[5];  // [512,128]
    const float* b2    = (const float*)d_in[6];  // [128]
    float* out = (float*)d_out;                  // [1024]

    const int B = 1024, N = 30000, D = 256, H1 = 512, H2 = 128;

    float *hidden, *sh, *h, *s2, *x2, *dist;
    cudaGetSymbolAddress((void**)&hidden, g_hidden);
    cudaGetSymbolAddress((void**)&sh, g_sh);
    cudaGetSymbolAddress((void**)&h, g_h);
    cudaGetSymbolAddress((void**)&s2, g_s2);
    cudaGetSymbolAddress((void**)&x2, g_x2);
    cudaGetSymbolAddress((void**)&dist, g_dist);

    dim3 t(TPB);
    const int nTilesN = (N + BM - 1) / BM;  // 235 row tiles for the sub set

    // sub_x path
    gemm_bias_relu<false><<<dim3(H1 / BN, nTilesN), t>>>(
        sub_x, W1, b1, hidden, nullptr, N, H1, D, D, H1, H1);
    gemm_bias_relu<true><<<dim3(H2 / BN, nTilesN), t>>>(
        hidden, W2, b2, sh, s2, N, H2, H1, H1, H2, H2);

    // x path (reuses hidden scratch; stream-ordered after step 2)
    gemm_bias_relu<false><<<dim3(H1 / BN, B / BM), t>>>(
        x, W1, b1, hidden, nullptr, B, H1, D, D, H1, H1);
    gemm_bias_relu<true><<<dim3(H2 / BN, B / BM), t>>>(
        hidden, W2, b2, h, x2, B, H2, H1, H1, H2, H2);

    // pairwise distances
    dist_kernel<<<dim3((N + BN - 1) / BN, B / BM), t>>>(
        h, sh, x2, s2, dist, B, N, H2);

    // softmax(-dist) @ sub_y
    softmax_out_kernel<<<B, TPB>>>(dist, sub_y, out, N);

    (void)in_sizes; (void)n_in; (void)out_size;
}

// round 9
// speedup vs baseline: 1.2557x; 1.2516x over previous
#include <cuda_runtime.h>
#include <cstdint>

// ---------------------------------------------------------------------------
// ModernNCA forward, fp32 FFMA2 GEMMs with cp.async double buffering.
//   1. hidden = relu(sub_x @ W1 + b1)                 [30000,512]
//   2. sh     = relu(hidden @ W2 + b2), s2=||sh||^2   [30000,128]
//   3. shT    = sh^T                                  [128,30000]
//   4. hidden = relu(x @ W1 + b1)                     [1024,512]
//   5. h      = relu(hidden @ W2 + b2)                [1024,128]; x2=||h||^2
//   6. fused dist+softmax partials per 128-col chunk: (min, sum e, sum e*y)
//   7. combine partials -> out[1024]
// ---------------------------------------------------------------------------

#define TPB 256
#define PART_STRIDE 240   // >= 235 chunks, float4 rows

static __device__ float  g_hidden[30000 * 512];
static __device__ float  g_sh[30000 * 128];
static __device__ float  g_shT[128 * 30000];
static __device__ float  g_h[1024 * 128];
static __device__ float  g_s2[30000];
static __device__ float  g_x2[1024];
static __device__ float4 g_part[1024 * PART_STRIDE];

// ---- packed f32x2 helpers --------------------------------------------------
__device__ __forceinline__ void fma2(unsigned long long& acc,
                                     unsigned long long a,
                                     unsigned long long b) {
    asm("fma.rn.f32x2 %0, %1, %2, %0;" : "+l"(acc) : "l"(a), "l"(b));
}
__device__ __forceinline__ unsigned long long pack2(float lo, float hi) {
    unsigned long long r;
    asm("mov.b64 %0, {%1, %2};" : "=l"(r) : "f"(lo), "f"(hi));
    return r;
}
__device__ __forceinline__ float2 unpack2(unsigned long long v) {
    float2 f;
    asm("mov.b64 {%0, %1}, %2;" : "=f"(f.x), "=f"(f.y) : "l"(v));
    return f;
}

// ---- cp.async helpers ------------------------------------------------------
__device__ __forceinline__ void cp_async16(void* sdst, const void* gsrc, bool pred) {
    uint32_t sa = (uint32_t)__cvta_generic_to_shared(sdst);
    int sz = pred ? 16 : 0;  // src-size 0 => zero-fill 16B
    asm volatile("cp.async.cg.shared.global [%0], [%1], 16, %2;"
                 :: "r"(sa), "l"(gsrc), "r"(sz) : "memory");
}
__device__ __forceinline__ void cp_commit() {
    asm volatile("cp.async.commit_group;" ::: "memory");
}
template <int N>
__device__ __forceinline__ void cp_wait() {
    asm volatile("cp.async.wait_group %0;" :: "n"(N) : "memory");
}

// ---------------------------------------------------------------------------
// Unified GEMM core.
//   A [M x K] row-major (lda=K stride), stored in smem as As[m][k] (natural).
//   B [K x N] row-major (ldb), stored as Bs[k][n] (natural).
// MODE 0: C = relu(A@B + bias)
// MODE 1: MODE 0 + row sum-of-squares (requires gridDim.x == 1, i.e. N == BN)
// MODE 2: dist + softmax partials: per row r and column-chunk blockIdx.x emit
//         (min_d, sum exp(min-d), sum exp(min-d)*y)  with d = sqrt(max(x2+s2-2ab,0)+eps)
// ---------------------------------------------------------------------------
template <int BM, int BN, int BK, int TM, int TN, int MODE>
__global__ void __launch_bounds__(TPB, 2)
gemm_core(const float* __restrict__ A, const float* __restrict__ B,
          const float* __restrict__ bias, float* __restrict__ C,
          float* __restrict__ sumsq,
          const float* __restrict__ x2g, const float* __restrict__ s2g,
          const float* __restrict__ yg, float4* __restrict__ part,
          int M, int N, int K, int lda, int ldb, int ldc) {
    static_assert(TPB == (BM / TM) * (BN / TN), "thread tiling");
    static_assert(BN / TN == 16, "shuffle width 16");

    __shared__ float As[2][BM][BK];
    __shared__ float Bs[2][BK][BN];

    const int blockN = blockIdx.x * BN;
    const int blockM = blockIdx.y * BM;
    const int tx = threadIdx.x & 15;         // BN/TN == 16 lanes
    const int ty = threadIdx.x >> 4;

    unsigned long long acc[TM][TN / 2];
#pragma unroll
    for (int i = 0; i < TM; i++)
#pragma unroll
        for (int j = 0; j < TN / 2; j++) acc[i][j] = 0ull;

    constexpr int BKq = BK / 4;   // 16B chunks per A row
    constexpr int BNq = BN / 4;   // 16B chunks per B row

    auto load_tiles = [&](int k0, int buf) {
        // A tile: rows blockM..+BM, cols k0..+BK  -> As[buf][row][k]
#pragma unroll
        for (int c = threadIdx.x; c < BM * BKq; c += TPB) {
            int row = c / BKq, kq = c % BKq;
            int gr = blockM + row;
            bool p = gr < M;
            const float* src = A + (size_t)(p ? gr : 0) * lda + k0 + kq * 4;
            cp_async16(&As[buf][row][kq * 4], src, p);
        }
        // B tile: rows k0..+BK, cols blockN..+BN -> Bs[buf][k][n]
#pragma unroll
        for (int c = threadIdx.x; c < BK * BNq; c += TPB) {
            int kk = c / BNq, nq = c % BNq;
            int gc = blockN + nq * 4;
            bool p = gc < N;
            const float* src = B + (size_t)(k0 + kk) * ldb + (p ? gc : 0);
            cp_async16(&Bs[buf][kk][nq * 4], src, p);
        }
    };

    const int nT = K / BK;
    load_tiles(0, 0);
    cp_commit();

    for (int t = 0; t < nT; t++) {
        if (t + 1 < nT) {
            load_tiles((t + 1) * BK, (t + 1) & 1);
            cp_commit();
            cp_wait<1>();
        } else {
            cp_wait<0>();
        }
        __syncthreads();

        const int buf = t & 1;
#pragma unroll
        for (int k4 = 0; k4 < BK / 4; k4++) {
            float4 a4[TM];
#pragma unroll
            for (int i = 0; i < TM; i++)
                a4[i] = *(const float4*)&As[buf][ty * TM + i][k4 * 4];
#pragma unroll
            for (int kk = 0; kk < 4; kk++) {
                unsigned long long bp[TN / 2];
                const unsigned long long* bq =
                    (const unsigned long long*)&Bs[buf][k4 * 4 + kk][tx * TN];
#pragma unroll
                for (int j = 0; j < TN / 2; j++) bp[j] = bq[j];
#pragma unroll
                for (int i = 0; i < TM; i++) {
                    float av = (kk == 0) ? a4[i].x : (kk == 1) ? a4[i].y
                             : (kk == 2) ? a4[i].z : a4[i].w;
                    unsigned long long ad = pack2(av, av);
#pragma unroll
                    for (int j = 0; j < TN / 2; j++) fma2(acc[i][j], ad, bp[j]);
                }
            }
        }
        __syncthreads();
    }

    // ---------------- epilogues ----------------
    if (MODE == 0 || MODE == 1) {
#pragma unroll
        for (int i = 0; i < TM; i++) {
            int grow = blockM + ty * TM + i;
            float ss = 0.f;
#pragma unroll
            for (int jp = 0; jp < TN / 2; jp++) {
                int col = blockN + tx * TN + 2 * jp;
                float2 c = unpack2(acc[i][jp]);
                c.x = fmaxf(c.x + bias[col], 0.f);
                c.y = fmaxf(c.y + bias[col + 1], 0.f);
                if (grow < M)
                    *(float2*)&C[(size_t)grow * ldc + col] = c;
                if (MODE == 1) ss += c.x * c.x + c.y * c.y;
            }
            if (MODE == 1) {
#pragma unroll
                for (int off = 8; off > 0; off >>= 1)
                    ss += __shfl_xor_sync(0xffffffffu, ss, off, 16);
                if (tx == 0 && grow < M) sumsq[grow] = ss;
            }
        }
    } else {  // MODE 2: fused distance + softmax partials
        const float INF = __int_as_float(0x7f800000);
        const int chunk = blockIdx.x;
#pragma unroll
        for (int i = 0; i < TM; i++) {
            int grow = blockM + ty * TM + i;      // M==1024, always valid
            float x2v = x2g[grow];
            float d[TN];
            float mloc = INF;
#pragma unroll
            for (int jp = 0; jp < TN / 2; jp++) {
                int col = blockN + tx * TN + 2 * jp;
                float2 c = unpack2(acc[i][jp]);
                float d0 = INF, d1 = INF;
                if (col < N)
                    d0 = sqrtf(fmaxf(x2v + s2g[col] - 2.0f * c.x, 0.f) + 1e-8f);
                if (col + 1 < N)
                    d1 = sqrtf(fmaxf(x2v + s2g[col + 1] - 2.0f * c.y, 0.f) + 1e-8f);
                d[2 * jp] = d0; d[2 * jp + 1] = d1;
                mloc = fminf(mloc, fminf(d0, d1));
            }
            float mrow = mloc;
#pragma unroll
            for (int off = 8; off > 0; off >>= 1)
                mrow = fminf(mrow, __shfl_xor_sync(0xffffffffu, mrow, off, 16));
            float s = 0.f, w = 0.f;
#pragma unroll
            for (int j = 0; j < TN; j++) {
                int col = blockN + tx * TN + j;
                if (col < N) {
                    float e = __expf(mrow - d[j]);
                    s += e;
                    w += e * yg[col];
                }
            }
#pragma unroll
            for (int off = 8; off > 0; off >>= 1) {
                s += __shfl_xor_sync(0xffffffffu, s, off, 16);
                w += __shfl_xor_sync(0xffffffffu, w, off, 16);
            }
            if (tx == 0)
                part[(size_t)grow * PART_STRIDE + chunk] = make_float4(mrow, s, w, 0.f);
        }
    }
}

// ---------------------------------------------------------------------------
// 32x32 tiled transpose: in[R][C] -> out[C][R]
// ---------------------------------------------------------------------------
__global__ void transpose_kernel(const float* __restrict__ in,
                                 float* __restrict__ out, int R, int C) {
    __shared__ float t[32][33];
    int c0 = blockIdx.x * 32, r0 = blockIdx.y * 32;
#pragma unroll
    for (int j = threadIdx.y; j < 32; j += 8) {
        int r = r0 + j, c = c0 + threadIdx.x;
        t[j][threadIdx.x] = (r < R && c < C) ? in[(size_t)r * C + c] : 0.f;
    }
    __syncthreads();
#pragma unroll
    for (int j = threadIdx.y; j < 32; j += 8) {
        int oc = c0 + j;           // output row (= input col)
        int orr = r0 + threadIdx.x;
        if (oc < C && orr < R)
            out[(size_t)oc * R + orr] = t[threadIdx.x][j];
    }
}

// ---------------------------------------------------------------------------
// Row sum-of-squares: x2[r] = sum_k h[r][k]^2   (K = 128, one warp per row)
// ---------------------------------------------------------------------------
__global__ void sumsq_kernel(const float* __restrict__ h, float* __restrict__ x2,
                             int K) {
    int row = blockIdx.x;
    int lane = threadIdx.x;
    const float4* r4 = (const float4*)(h + (size_t)row * K);
    float4 v = r4[lane];  // K/4 == 32 == warp size
    float ss = v.x * v.x + v.y * v.y + v.z * v.z + v.w * v.w;
#pragma unroll
    for (int off = 16; off > 0; off >>= 1)
        ss += __shfl_xor_sync(0xffffffffu, ss, off);
    if (lane == 0) x2[row] = ss;
}

// ---------------------------------------------------------------------------
// Combine per-chunk softmax partials -> out[b]
// ---------------------------------------------------------------------------
__global__ void combine_kernel(const float4* __restrict__ part,
                               float* __restrict__ out, int nChunks) {
    const int b = blockIdx.x;
    const float4* row = part + (size_t)b * PART_STRIDE;
    __shared__ float red[128];

    float m = __int_as_float(0x7f800000);
    for (int c = threadIdx.x; c < nChunks; c += 128)
        m = fminf(m, row[c].x);
    red[threadIdx.x] = m;
    __syncthreads();
    for (int s = 64; s > 0; s >>= 1) {
        if (threadIdx.x < s)
            red[threadIdx.x] = fminf(red[threadIdx.x], red[threadIdx.x + s]);
        __syncthreads();
    }
    const float M = red[0];
    __syncthreads();

    float S = 0.f, W = 0.f;
    for (int c = threadIdx.x; c < nChunks; c += 128) {
        float4 p = row[c];
        float f = __expf(M - p.x);
        S += f * p.y;
        W += f * p.z;
    }
    __shared__ float rs[128], rw[128];
    rs[threadIdx.x] = S; rw[threadIdx.x] = W;
    __syncthreads();
    for (int s = 64; s > 0; s >>= 1) {
        if (threadIdx.x < s) {
            rs[threadIdx.x] += rs[threadIdx.x + s];
            rw[threadIdx.x] += rw[threadIdx.x + s];
        }
        __syncthreads();
    }
    if (threadIdx.x == 0) out[b] = rw[0] / rs[0];
}

// ---------------------------------------------------------------------------
extern "C" void kernel_launch(void* const* d_in, const int* in_sizes, int n_in,
                              void* d_out, int out_size) {
    const float* x     = (const float*)d_in[0];  // [1024,256]
    const float* sub_x = (const float*)d_in[1];  // [30000,256]
    const float* sub_y = (const float*)d_in[2];  // [30000]
    const float* W1    = (const float*)d_in[3];  // [256,512]
    const float* b1    = (const float*)d_in[4];  // [512]
    const float* W2    = (const float*)d_in[5];  // [512,128]
    const float* b2    = (const float*)d_in[6];  // [128]
    float* out = (float*)d_out;                  // [1024]

    const int B = 1024, N = 30000, D = 256, H1 = 512, H2 = 128;
    const int nChunks = (N + 127) / 128;         // 235

    float *hidden, *sh, *shT, *h, *s2, *x2;
    float4* part;
    cudaGetSymbolAddress((void**)&hidden, g_hidden);
    cudaGetSymbolAddress((void**)&sh, g_sh);
    cudaGetSymbolAddress((void**)&shT, g_shT);
    cudaGetSymbolAddress((void**)&h, g_h);
    cudaGetSymbolAddress((void**)&s2, g_s2);
    cudaGetSymbolAddress((void**)&x2, g_x2);
    cudaGetSymbolAddress((void**)&part, g_part);

    dim3 t(TPB);

    // ---- sub path (big tiles) ----
    gemm_core<128, 128, 16, 8, 8, 0><<<dim3(H1 / 128, (N + 127) / 128), t>>>(
        sub_x, W1, b1, hidden, nullptr, nullptr, nullptr, nullptr, nullptr,
        N, H1, D, D, H1, H1);
    gemm_core<128, 128, 16, 8, 8, 1><<<dim3(1, (N + 127) / 128), t>>>(
        hidden, W2, b2, sh, s2, nullptr, nullptr, nullptr, nullptr,
        N, H2, H1, H1, H2, H2);
    transpose_kernel<<<dim3(H2 / 32, (N + 31) / 32), dim3(32, 8)>>>(sh, shT, N, H2);

    // ---- x path (small tiles to fill the chip) ----
    gemm_core<64, 64, 16, 4, 4, 0><<<dim3(H1 / 64, B / 64), t>>>(
        x, W1, b1, hidden, nullptr, nullptr, nullptr, nullptr, nullptr,
        B, H1, D, D, H1, H1);
    gemm_core<64, 32, 16, 4, 2, 0><<<dim3(H2 / 32, B / 64), t>>>(
        hidden, W2, b2, h, nullptr, nullptr, nullptr, nullptr, nullptr,
        B, H2, H1, H1, H2, H2);
    sumsq_kernel<<<B, 32>>>(h, x2, H2);

    // ---- fused distance + softmax partials ----
    gemm_core<128, 128, 16, 8, 8, 2><<<dim3(nChunks, B / 128), t>>>(
        h, shT, nullptr, nullptr, nullptr, x2, s2, sub_y, part,
        B, N, H2, H2, N, 0);

    // ---- combine ----
    combine_kernel<<<B, 128>>>(part, out, nChunks);

    (void)in_sizes; (void)n_in; (void)out_size;
}